// round 6
// baseline (speedup 1.0000x reference)
#include <cuda_runtime.h>
#include <cuda_bf16.h>
#include <cstdint>

#define NN 110
#define CC 4096
#define NPAD 128

#define BM 64
#define BN 64
#define BKC 64          // k per chunk
#define PITCH 72        // bf16 elems per smem row (64 + 8 pad)
#define NTH 256

// stage layout (bytes): A[m][k] hi/lo, B[k][n] hi/lo; rows of 72 bf16 = 144B
#define AH_OFF 0
#define AL_OFF 9216
#define BH_OFF 18432
#define BL_OFF 27648
#define STAGE  36864
#define DSMEM  (2 * STAGE)

// -------------------- scratch (zero-initialized device globals) ------------
__device__ __nv_bfloat16 g_xh[NPAD * CC], g_xl[NPAD * CC];
__device__ __nv_bfloat16 g_hh[NPAD * CC], g_hl[NPAD * CC];
__device__ __nv_bfloat16 g_ah[NPAD * CC], g_al[NPAD * CC];
__device__ __nv_bfloat16 g_oh[NPAD * CC], g_ol[NPAD * CC];
__device__ __nv_bfloat16 g_Mnh[NPAD * NPAD], g_Mnl[NPAD * NPAD];
__device__ __nv_bfloat16 g_Wlh[NPAD * NPAD], g_Wll[NPAD * NPAD];

// -------------------- helpers ----------------------------------------------
__device__ __forceinline__ uint32_t smem_u32(const void* p) {
    uint32_t a;
    asm("{ .reg .u64 t; cvta.to.shared.u64 t, %1; cvt.u32.u64 %0, t; }"
        : "=r"(a) : "l"(p));
    return a;
}

__device__ __forceinline__ void split2(float x0, float x1, uint32_t& hi, uint32_t& lo) {
    uint32_t h;
    asm("cvt.rn.bf16x2.f32 %0, %1, %2;" : "=r"(h) : "f"(x1), "f"(x0));
    float h0 = __uint_as_float(h << 16);
    float h1 = __uint_as_float(h & 0xFFFF0000u);
    float r0 = x0 - h0;
    float r1 = x1 - h1;
    asm("cvt.rn.bf16x2.f32 %0, %1, %2;" : "=r"(lo) : "f"(r1), "f"(r0));
    hi = h;
}

#define LDMX4(r, addr)                                                        \
    asm volatile("ldmatrix.sync.aligned.m8n8.x4.shared.b16 {%0,%1,%2,%3}, [%4];" \
        : "=r"((r)[0]), "=r"((r)[1]), "=r"((r)[2]), "=r"((r)[3]) : "r"(addr))

#define LDMX4T(r, addr)                                                       \
    asm volatile("ldmatrix.sync.aligned.m8n8.x4.trans.shared.b16 {%0,%1,%2,%3}, [%4];" \
        : "=r"((r)[0]), "=r"((r)[1]), "=r"((r)[2]), "=r"((r)[3]) : "r"(addr))

#define MMA_BF16(acc, a, b0, b1)                                              \
    asm volatile("mma.sync.aligned.m16n8k16.row.col.f32.bf16.bf16.f32 "       \
        "{%0,%1,%2,%3}, {%4,%5,%6,%7}, {%8,%9}, {%0,%1,%2,%3};"               \
        : "+f"((acc)[0]), "+f"((acc)[1]), "+f"((acc)[2]), "+f"((acc)[3])      \
        : "r"((a)[0]), "r"((a)[1]), "r"((a)[2]), "r"((a)[3]), "r"(b0), "r"(b1))

#define CP16(dst, src)                                                        \
    asm volatile("cp.async.cg.shared.global [%0], [%1], 16;" :: "r"(dst), "l"(src))
#define CP_COMMIT() asm volatile("cp.async.commit_group;" ::: "memory")
#define CP_WAIT(n)  asm volatile("cp.async.wait_group %0;" :: "n"(n) : "memory")

// ---------------------------------------------------------------------------
// Prep: split x into hi/lo bf16
// ---------------------------------------------------------------------------
__global__ void split_x_kernel(const float* __restrict__ src) {
    int e = (blockIdx.x * blockDim.x + threadIdx.x) * 8;
    if (e >= NN * CC) return;
    float4 a = *(const float4*)(src + e);
    float4 b = *(const float4*)(src + e + 4);
    uint4 hv, lv;
    split2(a.x, a.y, hv.x, lv.x);
    split2(a.z, a.w, hv.y, lv.y);
    split2(b.x, b.y, hv.z, lv.z);
    split2(b.z, b.w, hv.w, lv.w);
    *(uint4*)&g_xh[e] = hv;
    *(uint4*)&g_xl[e] = lv;
}

// ---------------------------------------------------------------------------
// Prep: Mn[j][i] = (adj[i][j]!=0)/max(deg_j,1); Wl padded; hi/lo bf16 out.
// ---------------------------------------------------------------------------
__global__ void prep_kernel(const int* __restrict__ adj, const float* __restrict__ Wl) {
    const int j = blockIdx.x;
    const int i = threadIdx.x;
    __shared__ int sdeg[NPAD];
    int a = (i < NN && j < NN) ? (adj[i * NN + j] != 0) : 0;
    sdeg[i] = a;
    __syncthreads();
#pragma unroll
    for (int s = 64; s > 0; s >>= 1) {
        if (i < s) sdeg[i] += sdeg[i + s];
        __syncthreads();
    }
    const int deg = sdeg[0];
    const float inv = (j < NN) ? 1.0f / (float)(deg > 1 ? deg : 1) : 0.0f;
    float mv = a ? inv : 0.0f;
    float wv = (i < NN && j < NN) ? Wl[j * NN + i] : 0.0f;
    __nv_bfloat16 mh = __float2bfloat16(mv);
    __nv_bfloat16 wh = __float2bfloat16(wv);
    g_Mnh[j * NPAD + i] = mh;
    g_Mnl[j * NPAD + i] = __float2bfloat16(mv - __bfloat162float(mh));
    g_Wlh[j * NPAD + i] = wh;
    g_Wll[j * NPAD + i] = __float2bfloat16(wv - __bfloat162float(wh));
}

// ---------------------------------------------------------------------------
// bf16-split HMMA GEMM, BM=64 x BN=64, 8 warps (2m x 2n x 2ksplit),
// warp tile 32x32, cp.async A (pre-split bf16), B fp32-convert or pre-split.
// ---------------------------------------------------------------------------
template<int BSPLIT, int OSPLIT>
__global__ __launch_bounds__(NTH, 1)
void tgemm(const __nv_bfloat16* __restrict__ Ah1, const __nv_bfloat16* __restrict__ Al1,
           int lda1, int ka1,
           const float* __restrict__ B1f,
           const __nv_bfloat16* __restrict__ B1h, const __nv_bfloat16* __restrict__ B1l,
           int ldb1,
           const __nv_bfloat16* __restrict__ Ah2, const __nv_bfloat16* __restrict__ Al2,
           int lda2, int ka2,
           const float* __restrict__ B2f, int ldb2,
           const float* __restrict__ bias, int bias_mode, int do_relu,
           float* __restrict__ C,
           __nv_bfloat16* __restrict__ Ch, __nv_bfloat16* __restrict__ Cl,
           int ldc, int Mreal)
{
    extern __shared__ __align__(16) char dsm[];
    const uint32_t sb = smem_u32(dsm);

    const int tid = threadIdx.x;
    const int wid = tid >> 5;
    const int lid = tid & 31;
    const int ms = wid & 1;
    const int ns = (wid >> 1) & 1;
    const int kh = wid >> 2;
    const int n0 = blockIdx.x * BN;
    const int m0cta = blockIdx.y * BM;

    // cp.async A loader mapping: 64 rows x 8 16B-chunks, thread -> (r, c & c+4)
    const int car = tid >> 2;
    const int cac = tid & 3;
    // fp32 B loader: thread -> (k-row, 16 n)
    const int bkq = tid >> 2;
    const int bnq = (tid & 3) * 16;

    const int T1 = ka1 / BKC;
    const int T2 = (Ah2 != nullptr) ? (ka2 / BKC) : 0;
    const int T  = T1 + T2;

    float acc[2][4][4];
#pragma unroll
    for (int a = 0; a < 2; ++a)
#pragma unroll
        for (int b = 0; b < 4; ++b)
#pragma unroll
            for (int c = 0; c < 4; ++c) acc[a][b][c] = 0.0f;

    // ldmatrix lane offsets (bytes within stage)
    const uint32_t aRow = (uint32_t)(ms * 32 + (lid & 15)) * PITCH + ((lid >> 4) & 1) * 8u;
    const uint32_t aoffH = AH_OFF + aRow * 2u;                 // + mt*16*PITCH*2 + kbyte
    const uint32_t bRowK = (uint32_t)(lid & 15) * PITCH;       // k row within tile
    const uint32_t bCol  = (uint32_t)(ns * 32 + (lid >> 4) * 8);
    const uint32_t boff  = BH_OFF + (bRowK + bCol) * 2u;       // + pair*32 + krow bytes
    const uint32_t kbA   = (uint32_t)kh * 64u;                 // k byte offset in A row
    const uint32_t kbB   = (uint32_t)kh * 32u * PITCH * 2u;    // k row byte offset in B

    float4 fbr[4];

    // ---- chunk-issue macros ----
#define CPA(T_)                                                                \
    do {                                                                       \
        int buf_ = (T_) & 1;                                                   \
        uint32_t db_ = sb + (uint32_t)buf_ * STAGE;                            \
        const __nv_bfloat16 *AhP, *AlP; int lda_, k0_;                         \
        if ((T_) < T1) { AhP = Ah1; AlP = Al1; lda_ = lda1; k0_ = (T_) * BKC; }\
        else { AhP = Ah2; AlP = Al2; lda_ = lda2; k0_ = ((T_) - T1) * BKC; }   \
        size_t gro_ = (size_t)(m0cta + car) * lda_ + k0_ + cac * 8;            \
        uint32_t so_ = ((uint32_t)car * PITCH + cac * 8u) * 2u;                \
        CP16(db_ + AH_OFF + so_,       AhP + gro_);                            \
        CP16(db_ + AH_OFF + so_ + 64u, AhP + gro_ + 32);                       \
        CP16(db_ + AL_OFF + so_,       AlP + gro_);                            \
        CP16(db_ + AL_OFF + so_ + 64u, AlP + gro_ + 32);                       \
        if (BSPLIT) {                                                          \
            size_t gb_ = (size_t)(k0_ + car) * ldb1 + n0 + cac * 8;            \
            CP16(db_ + BH_OFF + so_,       B1h + gb_);                         \
            CP16(db_ + BH_OFF + so_ + 64u, B1h + gb_ + 32);                    \
            CP16(db_ + BL_OFF + so_,       B1l + gb_);                         \
            CP16(db_ + BL_OFF + so_ + 64u, B1l + gb_ + 32);                    \
        }                                                                      \
    } while (0)

#define LDGB(T_)                                                               \
    do {                                                                       \
        const float* Bf_; int ldb_, k0_;                                       \
        if ((T_) < T1) { Bf_ = B1f; ldb_ = ldb1; k0_ = (T_) * BKC; }           \
        else { Bf_ = B2f; ldb_ = ldb2; k0_ = ((T_) - T1) * BKC; }              \
        const float* p_ = Bf_ + (size_t)(k0_ + bkq) * ldb_ + n0 + bnq;         \
        fbr[0] = *(const float4*)(p_ + 0);                                     \
        fbr[1] = *(const float4*)(p_ + 4);                                     \
        fbr[2] = *(const float4*)(p_ + 8);                                     \
        fbr[3] = *(const float4*)(p_ + 12);                                    \
    } while (0)

#define STSB(T_)                                                               \
    do {                                                                       \
        int buf_ = (T_) & 1;                                                   \
        char* st_ = dsm + buf_ * STAGE;                                        \
        uint4 hv0, hv1, lv0, lv1;                                              \
        split2(fbr[0].x, fbr[0].y, hv0.x, lv0.x);                              \
        split2(fbr[0].z, fbr[0].w, hv0.y, lv0.y);                              \
        split2(fbr[1].x, fbr[1].y, hv0.z, lv0.z);                              \
        split2(fbr[1].z, fbr[1].w, hv0.w, lv0.w);                              \
        split2(fbr[2].x, fbr[2].y, hv1.x, lv1.x);                              \
        split2(fbr[2].z, fbr[2].w, hv1.y, lv1.y);                              \
        split2(fbr[3].x, fbr[3].y, hv1.z, lv1.z);                              \
        split2(fbr[3].z, fbr[3].w, hv1.w, lv1.w);                              \
        uint32_t o_ = ((uint32_t)bkq * PITCH + (uint32_t)bnq) * 2u;            \
        *(uint4*)(st_ + BH_OFF + o_)       = hv0;                              \
        *(uint4*)(st_ + BH_OFF + o_ + 16u) = hv1;                              \
        *(uint4*)(st_ + BL_OFF + o_)       = lv0;                              \
        *(uint4*)(st_ + BL_OFF + o_ + 16u) = lv1;                              \
    } while (0)

    // ---- prologue: chunks 0 and 1 in flight ----
    if (!BSPLIT) { LDGB(0); }
    CPA(0); CP_COMMIT();
    if (!BSPLIT) { STSB(0); }
    if (T > 1) {
        if (!BSPLIT) LDGB(1);
        CPA(1); CP_COMMIT();
    } else {
        CP_COMMIT();   // keep group numbering simple
    }
    CP_WAIT(1);
    __syncthreads();

    for (int t = 0; t < T; ++t) {
        const uint32_t base = sb + (uint32_t)(t & 1) * STAGE;

        // ---- MMA: 2 k-steps of 16 (this warp's k-half) ----
#pragma unroll
        for (int ks = 0; ks < 2; ++ks) {
            const uint32_t kA = kbA + (uint32_t)ks * 32u;            // bytes
            const uint32_t kB = kbB + (uint32_t)ks * 16u * PITCH * 2u;
            uint32_t ah[2][4], al[2][4], bh[2][4], bl[2][4];
            LDMX4(ah[0], base + aoffH + kA);
            LDMX4(ah[1], base + aoffH + 16u * PITCH * 2u + kA);
            LDMX4(al[0], base + aoffH + (AL_OFF - AH_OFF) + kA);
            LDMX4(al[1], base + aoffH + (AL_OFF - AH_OFF) + 16u * PITCH * 2u + kA);
            LDMX4T(bh[0], base + boff + kB);
            LDMX4T(bh[1], base + boff + 32u + kB);
            LDMX4T(bl[0], base + boff + (BL_OFF - BH_OFF) + kB);
            LDMX4T(bl[1], base + boff + (BL_OFF - BH_OFF) + 32u + kB);
#pragma unroll
            for (int mt = 0; mt < 2; ++mt)
#pragma unroll
                for (int nt = 0; nt < 4; ++nt) {
                    const int gp = nt >> 1, ix = (nt & 1) * 2;
                    MMA_BF16(acc[mt][nt], ah[mt], bh[gp][ix], bh[gp][ix + 1]);
                    MMA_BF16(acc[mt][nt], ah[mt], bl[gp][ix], bl[gp][ix + 1]);
                    MMA_BF16(acc[mt][nt], al[mt], bh[gp][ix], bh[gp][ix + 1]);
                }
        }

        // ---- stage t+1 B (fp32 path), then rotate pipeline ----
        if (!BSPLIT && t + 1 < T) STSB(t + 1);
        __syncthreads();                      // all reads of buf(t) done
        if (t + 2 < T) {
            if (!BSPLIT) LDGB(t + 2);
            CPA(t + 2); CP_COMMIT();
            CP_WAIT(1);                       // chunk t+1 A (and B) landed
        } else {
            CP_WAIT(0);
        }
        __syncthreads();                      // everyone sees t+1 data
    }
#undef CPA
#undef LDGB
#undef STSB

    // ---- k-split reduction through smem ----
    {
        const int widx = ms * 2 + ns;
        float4* red = (float4*)(dsm) + (size_t)(widx * 32 + lid) * 8;
        if (kh == 1) {
#pragma unroll
            for (int j = 0; j < 8; ++j)
                red[j] = make_float4(acc[j >> 2][j & 3][0], acc[j >> 2][j & 3][1],
                                     acc[j >> 2][j & 3][2], acc[j >> 2][j & 3][3]);
        }
        __syncthreads();
        if (kh == 0) {
#pragma unroll
            for (int j = 0; j < 8; ++j) {
                float4 v = red[j];
                acc[j >> 2][j & 3][0] += v.x;
                acc[j >> 2][j & 3][1] += v.y;
                acc[j >> 2][j & 3][2] += v.z;
                acc[j >> 2][j & 3][3] += v.w;
            }
        }
    }

    // ---- epilogue (kh==0 warps) ----
    if (kh == 0) {
        const int g  = lid >> 2;
        const int tq = lid & 3;
#pragma unroll
        for (int mt = 0; mt < 2; ++mt) {
#pragma unroll
            for (int nt = 0; nt < 4; ++nt) {
                int col = n0 + ns * 32 + nt * 8 + tq * 2;
                float bc0 = 0.f, bc1 = 0.f;
                if (bias_mode == 1) { bc0 = bias[col]; bc1 = bias[col + 1]; }
#pragma unroll
                for (int half = 0; half < 2; ++half) {
                    int m = m0cta + ms * 32 + mt * 16 + g + half * 8;
                    if (m >= Mreal) continue;
                    float rb = (bias_mode == 2) ? bias[m] : 0.0f;
                    float vx = acc[mt][nt][half * 2 + 0] + bc0 + rb;
                    float vy = acc[mt][nt][half * 2 + 1] + bc1 + rb;
                    if (do_relu) { vx = fmaxf(vx, 0.f); vy = fmaxf(vy, 0.f); }
                    if (OSPLIT) {
                        uint32_t hw, lw;
                        split2(vx, vy, hw, lw);
                        size_t off = (size_t)m * ldc + col;
                        *(uint32_t*)(Ch + off) = hw;
                        *(uint32_t*)(Cl + off) = lw;
                    } else {
                        *(float2*)&C[(size_t)m * ldc + col] = make_float2(vx, vy);
                    }
                }
            }
        }
    }
}

// ---------------------------------------------------------------------------
extern "C" void kernel_launch(void* const* d_in, const int* in_sizes, int n_in,
                              void* d_out, int out_size)
{
    const float* x   = (const float*)d_in[0];
    const int*   adj = (const int*)  d_in[1];
    const float* W2  = (const float*)d_in[2];
    const float* b2  = (const float*)d_in[3];
    const float* W1  = (const float*)d_in[4];
    const float* b1  = (const float*)d_in[5];
    const float* Wl  = (const float*)d_in[6];
    const float* bl  = (const float*)d_in[7];
    float* out = (float*)d_out;

    __nv_bfloat16 *xh, *xl, *hh, *hl, *ah, *al, *oh, *ol, *Mnh, *Mnl, *Wlh, *Wll;
    cudaGetSymbolAddress((void**)&xh, g_xh);   cudaGetSymbolAddress((void**)&xl, g_xl);
    cudaGetSymbolAddress((void**)&hh, g_hh);   cudaGetSymbolAddress((void**)&hl, g_hl);
    cudaGetSymbolAddress((void**)&ah, g_ah);   cudaGetSymbolAddress((void**)&al, g_al);
    cudaGetSymbolAddress((void**)&oh, g_oh);   cudaGetSymbolAddress((void**)&ol, g_ol);
    cudaGetSymbolAddress((void**)&Mnh, g_Mnh); cudaGetSymbolAddress((void**)&Mnl, g_Mnl);
    cudaGetSymbolAddress((void**)&Wlh, g_Wlh); cudaGetSymbolAddress((void**)&Wll, g_Wll);

    cudaFuncSetAttribute(tgemm<0,1>, cudaFuncAttributeMaxDynamicSharedMemorySize, DSMEM);
    cudaFuncSetAttribute(tgemm<1,1>, cudaFuncAttributeMaxDynamicSharedMemorySize, DSMEM);
    cudaFuncSetAttribute(tgemm<1,0>, cudaFuncAttributeMaxDynamicSharedMemorySize, DSMEM);

    dim3 g(CC / BN, 2), b(NTH);   // 64 x 2 = 128 CTAs

    split_x_kernel<<<(NN * CC / 8 + 255) / 256, 256>>>(x);
    prep_kernel<<<NPAD, NPAD>>>(adj, Wl);

    // K1: h = x @ W2 + b2
    tgemm<0,1><<<g, b, DSMEM>>>(xh, xl, CC, CC,
                                W2, nullptr, nullptr, CC,
                                nullptr, nullptr, 0, 0, nullptr, 0,
                                b2, 1, 0,
                                nullptr, hh, hl, CC, NN);
    // K2: aggr = Mn @ h
    tgemm<1,1><<<g, b, DSMEM>>>(Mnh, Mnl, NPAD, NPAD,
                                nullptr, hh, hl, CC,
                                nullptr, nullptr, 0, 0, nullptr, 0,
                                nullptr, 0, 0,
                                nullptr, ah, al, CC, NN);
    // K3: out1 = relu(h @ W1_top + aggr @ W1_bot + b1)
    tgemm<0,1><<<g, b, DSMEM>>>(hh, hl, CC, CC,
                                W1, nullptr, nullptr, CC,
                                ah, al, CC, CC, W1 + (size_t)CC * CC, CC,
                                b1, 1, 1,
                                nullptr, oh, ol, CC, NN);
    // K4: out = Wlp @ out1 + bl[:, None]
    tgemm<1,0><<<g, b, DSMEM>>>(Wlh, Wll, NPAD, NPAD,
                                nullptr, oh, ol, CC,
                                nullptr, nullptr, 0, 0, nullptr, 0,
                                bl, 2, 0,
                                out, nullptr, nullptr, CC, NN);
}

// round 7
// speedup vs baseline: 1.5935x; 1.5935x over previous
#include <cuda_runtime.h>
#include <cuda_bf16.h>
#include <cstdint>

#define NN 110
#define CC 4096
#define NPAD 128

#define BM 128
#define BN 64
#define BKC 64          // fp32 k per chunk
#define PITCH 72        // bf16 elems per smem row (64 + 8 pad)
#define NTH 256

// stage layout (bytes): A[m][k] hi/lo (128x64), B[k][n] hi/lo (64x64)
#define AH_OFF 0
#define AL_OFF 18432
#define BH_OFF 36864
#define BL_OFF 46080
#define STAGE  55296
#define DSMEM  (2 * STAGE)

#define PS (NPAD * CC)   // partial buffer stride

// -------------------- scratch (zero-initialized device globals) ------------
__device__ float g_h   [NPAD * CC];
__device__ float g_aggr[NPAD * CC];
__device__ float g_out1[NPAD * CC];
__device__ float g_Mn  [NPAD * NPAD];
__device__ float g_Wlp [NPAD * NPAD];
__device__ float g_P   [2 * PS];

// -------------------- helpers ----------------------------------------------
__device__ __forceinline__ uint32_t smem_u32(const void* p) {
    uint32_t a;
    asm("{ .reg .u64 t; cvta.to.shared.u64 t, %1; cvt.u32.u64 %0, t; }"
        : "=r"(a) : "l"(p));
    return a;
}

__device__ __forceinline__ void split2(float x0, float x1, uint32_t& hi, uint32_t& lo) {
    uint32_t h;
    asm("cvt.rn.bf16x2.f32 %0, %1, %2;" : "=r"(h) : "f"(x1), "f"(x0));
    float h0 = __uint_as_float(h << 16);
    float h1 = __uint_as_float(h & 0xFFFF0000u);
    float r0 = x0 - h0;
    float r1 = x1 - h1;
    asm("cvt.rn.bf16x2.f32 %0, %1, %2;" : "=r"(lo) : "f"(r1), "f"(r0));
    hi = h;
}

#define LDMX4(r, addr)                                                        \
    asm volatile("ldmatrix.sync.aligned.m8n8.x4.shared.b16 {%0,%1,%2,%3}, [%4];" \
        : "=r"((r)[0]), "=r"((r)[1]), "=r"((r)[2]), "=r"((r)[3]) : "r"(addr))

#define LDMX4T(r, addr)                                                       \
    asm volatile("ldmatrix.sync.aligned.m8n8.x4.trans.shared.b16 {%0,%1,%2,%3}, [%4];" \
        : "=r"((r)[0]), "=r"((r)[1]), "=r"((r)[2]), "=r"((r)[3]) : "r"(addr))

#define MMA_BF16(acc, a, b0, b1)                                              \
    asm volatile("mma.sync.aligned.m16n8k16.row.col.f32.bf16.bf16.f32 "       \
        "{%0,%1,%2,%3}, {%4,%5,%6,%7}, {%8,%9}, {%0,%1,%2,%3};"               \
        : "+f"((acc)[0]), "+f"((acc)[1]), "+f"((acc)[2]), "+f"((acc)[3])      \
        : "r"((a)[0]), "r"((a)[1]), "r"((a)[2]), "r"((a)[3]), "r"(b0), "r"(b1))

// ---------------------------------------------------------------------------
// Prep: Mn[j][i] = (adj[i][j]!=0)/max(deg_j,1); Wl padded to 128 (fp32).
// ---------------------------------------------------------------------------
__global__ void prep_kernel(const int* __restrict__ adj, const float* __restrict__ Wl) {
    const int j = blockIdx.x;
    const int i = threadIdx.x;
    __shared__ int sdeg[NPAD];
    int a = (i < NN && j < NN) ? (adj[i * NN + j] != 0) : 0;
    sdeg[i] = a;
    __syncthreads();
#pragma unroll
    for (int s = 64; s > 0; s >>= 1) {
        if (i < s) sdeg[i] += sdeg[i + s];
        __syncthreads();
    }
    const int deg = sdeg[0];
    const float inv = (j < NN) ? 1.0f / (float)(deg > 1 ? deg : 1) : 0.0f;
    g_Mn [j * NPAD + i] = a ? inv : 0.0f;
    g_Wlp[j * NPAD + i] = (i < NN && j < NN) ? Wl[j * NN + i] : 0.0f;
}

// ---------------------------------------------------------------------------
// Combine: out = act(P0 + P1 + bias_col) ; fp32, 110x4096, float4 lanes
// ---------------------------------------------------------------------------
__global__ void combine_kernel(const float* __restrict__ P,
                               const float* __restrict__ bias, int do_relu,
                               float* __restrict__ out) {
    int e = (blockIdx.x * blockDim.x + threadIdx.x) * 4;
    if (e >= NN * CC) return;
    float4 p0 = *(const float4*)(P + e);
    float4 p1 = *(const float4*)(P + PS + e);
    float4 bv = *(const float4*)(bias + (e & (CC - 1)));
    float4 v;
    v.x = p0.x + p1.x + bv.x;
    v.y = p0.y + p1.y + bv.y;
    v.z = p0.z + p1.z + bv.z;
    v.w = p0.w + p1.w + bv.w;
    if (do_relu) {
        v.x = fmaxf(v.x, 0.f); v.y = fmaxf(v.y, 0.f);
        v.z = fmaxf(v.z, 0.f); v.w = fmaxf(v.w, 0.f);
    }
    *(float4*)(out + e) = v;
}

// ---------------------------------------------------------------------------
// bf16-split HMMA GEMM. CTA tile 128x64, 8 warps (4m x 2n), warp tile 32x32.
// blockIdx.y selects operand slice (k-split across grid). Double-buffered.
// partial=1: raw fp32 accum to C + slice*PS. partial=0: bias/relu epilogue.
// ---------------------------------------------------------------------------
__global__ __launch_bounds__(NTH, 1)
void tgemm(const float* __restrict__ A1, int lda1, int ka1,
           const float* __restrict__ B1, int ldb1,
           const float* __restrict__ A2, int lda2, int ka2,
           const float* __restrict__ B2, int ldb2,
           const float* __restrict__ bias, int bias_mode, int do_relu,
           int partial,
           float* __restrict__ C, int ldc, int Mreal)
{
    extern __shared__ __align__(16) char dsm[];
    const uint32_t sb = smem_u32(dsm);

    const int tid = threadIdx.x;
    const int wid = tid >> 5;
    const int lid = tid & 31;
    const int ms = wid & 3;          // 4 m-warps, base ms*32
    const int ns = wid >> 2;         // 2 n-warps, base ns*32
    const int n0 = blockIdx.x * BN;
    const int slice = blockIdx.y;

    const float* A = slice ? A2 : A1;
    const float* B = slice ? B2 : B1;
    const int lda = slice ? lda2 : lda1;
    const int ldb = slice ? ldb2 : ldb1;
    const int T = (slice ? ka2 : ka1) / BKC;

    // A loader: 128 rows x 64 k fp32, float4, 8 passes (16 threads/row)
    const int alrow = tid >> 4;
    const int alc   = (tid & 15) * 4;
    // B loader: 64 k x 64 n; thread -> (k row, 16 n)
    const int bkq = tid >> 2;
    const int bnq = (tid & 3) * 16;

    float acc[2][4][4];
#pragma unroll
    for (int a = 0; a < 2; ++a)
#pragma unroll
        for (int b = 0; b < 4; ++b)
#pragma unroll
            for (int c = 0; c < 4; ++c) acc[a][b][c] = 0.0f;

    // A fragment lane offsets (R5-validated non-trans layout)
    const uint32_t aoffH = AH_OFF +
        (((uint32_t)(ms * 32 + (lid & 15)) * PITCH) + ((lid >> 4) & 1) * 8u) * 2u;
    // B fragment lane offsets (R6-validated trans layout, [k][n] smem)
    const uint32_t boff = BH_OFF +
        (((uint32_t)(lid & 15) * PITCH) + (uint32_t)(ns * 32 + (lid >> 4) * 8)) * 2u;

    float4 fa[8];
    float4 fbr[4];
    const float4 f4z = make_float4(0.f, 0.f, 0.f, 0.f);

#define LOADG(T_)                                                              \
    do {                                                                       \
        int k0_ = (T_) * BKC;                                                  \
        _Pragma("unroll")                                                      \
        for (int p = 0; p < 8; ++p) {                                          \
            int m = p * 16 + alrow;                                            \
            fa[p] = (m < Mreal) ? *(const float4*)(A + (size_t)m * lda + k0_ + alc) : f4z; \
        }                                                                      \
        const float* p_ = B + (size_t)(k0_ + bkq) * ldb + n0 + bnq;            \
        fbr[0] = *(const float4*)(p_ + 0);                                     \
        fbr[1] = *(const float4*)(p_ + 4);                                     \
        fbr[2] = *(const float4*)(p_ + 8);                                     \
        fbr[3] = *(const float4*)(p_ + 12);                                    \
    } while (0)

#define STORE_STAGE(bufsel)                                                    \
    do {                                                                       \
        char* st = dsm + (bufsel) * STAGE;                                     \
        _Pragma("unroll")                                                      \
        for (int p = 0; p < 8; ++p) {                                          \
            int row = p * 16 + alrow;                                          \
            uint32_t h0, l0, h1, l1;                                           \
            split2(fa[p].x, fa[p].y, h0, l0);                                  \
            split2(fa[p].z, fa[p].w, h1, l1);                                  \
            uint32_t off = ((uint32_t)row * PITCH + (uint32_t)alc) * 2u;       \
            *(uint2*)(st + AH_OFF + off) = make_uint2(h0, h1);                 \
            *(uint2*)(st + AL_OFF + off) = make_uint2(l0, l1);                 \
        }                                                                      \
        {                                                                      \
            uint4 hv0, hv1, lv0, lv1;                                          \
            split2(fbr[0].x, fbr[0].y, hv0.x, lv0.x);                          \
            split2(fbr[0].z, fbr[0].w, hv0.y, lv0.y);                          \
            split2(fbr[1].x, fbr[1].y, hv0.z, lv0.z);                          \
            split2(fbr[1].z, fbr[1].w, hv0.w, lv0.w);                          \
            split2(fbr[2].x, fbr[2].y, hv1.x, lv1.x);                          \
            split2(fbr[2].z, fbr[2].w, hv1.y, lv1.y);                          \
            split2(fbr[3].x, fbr[3].y, hv1.z, lv1.z);                          \
            split2(fbr[3].z, fbr[3].w, hv1.w, lv1.w);                          \
            uint32_t o_ = ((uint32_t)bkq * PITCH + (uint32_t)bnq) * 2u;        \
            *(uint4*)(st + BH_OFF + o_)       = hv0;                           \
            *(uint4*)(st + BH_OFF + o_ + 16u) = hv1;                           \
            *(uint4*)(st + BL_OFF + o_)       = lv0;                           \
            *(uint4*)(st + BL_OFF + o_ + 16u) = lv1;                           \
        }                                                                      \
    } while (0)

    // ---- prologue ----
    LOADG(0);
    STORE_STAGE(0);
    if (T > 1) LOADG(1);
    __syncthreads();

    for (int t = 0; t < T; ++t) {
        const uint32_t base = sb + (uint32_t)(t & 1) * STAGE;

        // ---- MMA: 4 k-steps of 16 ----
#pragma unroll
        for (int ks = 0; ks < 4; ++ks) {
            const uint32_t kA = (uint32_t)ks * 32u;
            const uint32_t kB = (uint32_t)ks * 16u * PITCH * 2u;
            uint32_t ah[2][4], al[2][4], bh[2][4], bl[2][4];
            LDMX4(ah[0], base + aoffH + kA);
            LDMX4(ah[1], base + aoffH + 16u * PITCH * 2u + kA);
            LDMX4(al[0], base + aoffH + (AL_OFF - AH_OFF) + kA);
            LDMX4(al[1], base + aoffH + (AL_OFF - AH_OFF) + 16u * PITCH * 2u + kA);
            LDMX4T(bh[0], base + boff + kB);
            LDMX4T(bh[1], base + boff + 32u + kB);
            LDMX4T(bl[0], base + boff + (BL_OFF - BH_OFF) + kB);
            LDMX4T(bl[1], base + boff + (BL_OFF - BH_OFF) + 32u + kB);
#pragma unroll
            for (int mt = 0; mt < 2; ++mt)
#pragma unroll
                for (int nt = 0; nt < 4; ++nt) {
                    const int gp = nt >> 1, ix = (nt & 1) * 2;
                    MMA_BF16(acc[mt][nt], ah[mt], bh[gp][ix], bh[gp][ix + 1]);
                    MMA_BF16(acc[mt][nt], ah[mt], bl[gp][ix], bl[gp][ix + 1]);
                    MMA_BF16(acc[mt][nt], al[mt], bh[gp][ix], bh[gp][ix + 1]);
                }
        }

        // ---- stage t+1, prefetch t+2 ----
        if (t + 1 < T) STORE_STAGE((t + 1) & 1);
        if (t + 2 < T) LOADG(t + 2);

        __syncthreads();
    }
#undef LOADG
#undef STORE_STAGE

    // ---- epilogue ----
    const int g  = lid >> 2;
    const int tq = lid & 3;
    float* Pout = C + (size_t)slice * PS;
#pragma unroll
    for (int mt = 0; mt < 2; ++mt) {
#pragma unroll
        for (int nt = 0; nt < 4; ++nt) {
            int col = n0 + ns * 32 + nt * 8 + tq * 2;
            float bc0 = 0.f, bc1 = 0.f;
            if (!partial && bias_mode == 1) { bc0 = bias[col]; bc1 = bias[col + 1]; }
#pragma unroll
            for (int half = 0; half < 2; ++half) {
                int m = ms * 32 + mt * 16 + g + half * 8;
                if (m >= Mreal) continue;
                float vx = acc[mt][nt][half * 2 + 0];
                float vy = acc[mt][nt][half * 2 + 1];
                if (partial) {
                    *(float2*)&Pout[(size_t)m * ldc + col] = make_float2(vx, vy);
                } else {
                    float rb = (bias_mode == 2) ? bias[m] : 0.0f;
                    vx += bc0 + rb;
                    vy += bc1 + rb;
                    if (do_relu) { vx = fmaxf(vx, 0.f); vy = fmaxf(vy, 0.f); }
                    *(float2*)&C[(size_t)m * ldc + col] = make_float2(vx, vy);
                }
            }
        }
    }
}

// ---------------------------------------------------------------------------
extern "C" void kernel_launch(void* const* d_in, const int* in_sizes, int n_in,
                              void* d_out, int out_size)
{
    const float* x   = (const float*)d_in[0];
    const int*   adj = (const int*)  d_in[1];
    const float* W2  = (const float*)d_in[2];
    const float* b2  = (const float*)d_in[3];
    const float* W1  = (const float*)d_in[4];
    const float* b1  = (const float*)d_in[5];
    const float* Wl  = (const float*)d_in[6];
    const float* bl  = (const float*)d_in[7];
    float* out = (float*)d_out;

    float *h, *aggr, *out1, *Mn, *Wlp, *P;
    cudaGetSymbolAddress((void**)&h,    g_h);
    cudaGetSymbolAddress((void**)&aggr, g_aggr);
    cudaGetSymbolAddress((void**)&out1, g_out1);
    cudaGetSymbolAddress((void**)&Mn,   g_Mn);
    cudaGetSymbolAddress((void**)&Wlp,  g_Wlp);
    cudaGetSymbolAddress((void**)&P,    g_P);

    cudaFuncSetAttribute(tgemm, cudaFuncAttributeMaxDynamicSharedMemorySize, DSMEM);

    dim3 b(NTH);
    dim3 gs(CC / BN, 2);   // 64 x 2 = 128 CTAs (k-split)
    dim3 gd(CC / BN, 1);   // 64 CTAs (direct)
    int cgrid = (NN * CC / 4 + 255) / 256;

    prep_kernel<<<NPAD, NPAD>>>(adj, Wl);

    // K1 (split): P = x @ W2  (k halves 0:2048, 2048:4096)
    tgemm<<<gs, b, DSMEM>>>(x, CC, 2048, W2, CC,
                            x + 2048, CC, 2048, W2 + (size_t)2048 * CC, CC,
                            nullptr, 0, 0, /*partial=*/1,
                            P, CC, NN);
    // h = P0 + P1 + b2
    combine_kernel<<<cgrid, 256>>>(P, b2, 0, h);

    // K2 (direct): aggr = Mn @ h
    tgemm<<<gd, b, DSMEM>>>(Mn, NPAD, NPAD, h, CC,
                            nullptr, 0, 0, nullptr, 0,
                            nullptr, 0, 0, /*partial=*/0,
                            aggr, CC, NN);

    // K3 (split): P = h @ W1_top  ||  aggr @ W1_bot
    tgemm<<<gs, b, DSMEM>>>(h, CC, CC, W1, CC,
                            aggr, CC, CC, W1 + (size_t)CC * CC, CC,
                            nullptr, 0, 0, /*partial=*/1,
                            P, CC, NN);
    // out1 = relu(P0 + P1 + b1)
    combine_kernel<<<cgrid, 256>>>(P, b1, 1, out1);

    // K4 (direct): out = Wlp @ out1 + bl[:,None]
    tgemm<<<gd, b, DSMEM>>>(Wlp, NPAD, NPAD, out1, CC,
                            nullptr, 0, 0, nullptr, 0,
                            bl, 2, 0, /*partial=*/0,
                            out, CC, NN);
}

// round 8
// speedup vs baseline: 1.6403x; 1.0293x over previous
#include <cuda_runtime.h>
#include <cuda_bf16.h>
#include <cstdint>

#define NN 110
#define CC 4096
#define NPAD 128

#define BM 128
#define BKC 64          // fp32 k per chunk
#define PITCHA 72       // bf16 elems per A smem row (64 + 8 pad)
#define NTH 256

#define PS (NPAD * CC)  // partial buffer stride

// -------------------- scratch (zero-initialized device globals) ------------
__device__ float g_h   [NPAD * CC];
__device__ float g_aggr[NPAD * CC];
__device__ float g_out1[NPAD * CC];
__device__ float g_Mn  [NPAD * NPAD];
__device__ float g_Wlp [NPAD * NPAD];
__device__ float g_P   [4 * PS];

// -------------------- helpers ----------------------------------------------
__device__ __forceinline__ uint32_t smem_u32(const void* p) {
    uint32_t a;
    asm("{ .reg .u64 t; cvta.to.shared.u64 t, %1; cvt.u32.u64 %0, t; }"
        : "=r"(a) : "l"(p));
    return a;
}

__device__ __forceinline__ void split2(float x0, float x1, uint32_t& hi, uint32_t& lo) {
    uint32_t h;
    asm("cvt.rn.bf16x2.f32 %0, %1, %2;" : "=r"(h) : "f"(x1), "f"(x0));
    float h0 = __uint_as_float(h << 16);
    float h1 = __uint_as_float(h & 0xFFFF0000u);
    float r0 = x0 - h0;
    float r1 = x1 - h1;
    asm("cvt.rn.bf16x2.f32 %0, %1, %2;" : "=r"(lo) : "f"(r1), "f"(r0));
    hi = h;
}

#define LDMX4(r, addr)                                                        \
    asm volatile("ldmatrix.sync.aligned.m8n8.x4.shared.b16 {%0,%1,%2,%3}, [%4];" \
        : "=r"((r)[0]), "=r"((r)[1]), "=r"((r)[2]), "=r"((r)[3]) : "r"(addr))

#define LDMX4T(r, addr)                                                       \
    asm volatile("ldmatrix.sync.aligned.m8n8.x4.trans.shared.b16 {%0,%1,%2,%3}, [%4];" \
        : "=r"((r)[0]), "=r"((r)[1]), "=r"((r)[2]), "=r"((r)[3]) : "r"(addr))

#define MMA_BF16(acc, a, b0, b1)                                              \
    asm volatile("mma.sync.aligned.m16n8k16.row.col.f32.bf16.bf16.f32 "       \
        "{%0,%1,%2,%3}, {%4,%5,%6,%7}, {%8,%9}, {%0,%1,%2,%3};"               \
        : "+f"((acc)[0]), "+f"((acc)[1]), "+f"((acc)[2]), "+f"((acc)[3])      \
        : "r"((a)[0]), "r"((a)[1]), "r"((a)[2]), "r"((a)[3]), "r"(b0), "r"(b1))

// ---------------------------------------------------------------------------
// Prep: Mn[j][i] = (adj[i][j]!=0)/max(deg_j,1); Wl padded to 128 (fp32).
// ---------------------------------------------------------------------------
__global__ void prep_kernel(const int* __restrict__ adj, const float* __restrict__ Wl) {
    const int j = blockIdx.x;
    const int i = threadIdx.x;
    __shared__ int sdeg[NPAD];
    int a = (i < NN && j < NN) ? (adj[i * NN + j] != 0) : 0;
    sdeg[i] = a;
    __syncthreads();
#pragma unroll
    for (int s = 64; s > 0; s >>= 1) {
        if (i < s) sdeg[i] += sdeg[i + s];
        __syncthreads();
    }
    const int deg = sdeg[0];
    const float inv = (j < NN) ? 1.0f / (float)(deg > 1 ? deg : 1) : 0.0f;
    g_Mn [j * NPAD + i] = a ? inv : 0.0f;
    g_Wlp[j * NPAD + i] = (i < NN && j < NN) ? Wl[j * NN + i] : 0.0f;
}

// ---------------------------------------------------------------------------
// Combine: out = act(sum_{s<4} P_s + bias_col)
// ---------------------------------------------------------------------------
__global__ void combine_kernel(const float* __restrict__ P,
                               const float* __restrict__ bias, int do_relu,
                               float* __restrict__ out) {
    int e = (blockIdx.x * blockDim.x + threadIdx.x) * 4;
    if (e >= NN * CC) return;
    float4 p0 = *(const float4*)(P + e);
    float4 p1 = *(const float4*)(P + PS + e);
    float4 p2 = *(const float4*)(P + 2 * PS + e);
    float4 p3 = *(const float4*)(P + 3 * PS + e);
    float4 bv = *(const float4*)(bias + (e & (CC - 1)));
    float4 v;
    v.x = (p0.x + p1.x) + (p2.x + p3.x) + bv.x;
    v.y = (p0.y + p1.y) + (p2.y + p3.y) + bv.y;
    v.z = (p0.z + p1.z) + (p2.z + p3.z) + bv.z;
    v.w = (p0.w + p1.w) + (p2.w + p3.w) + bv.w;
    if (do_relu) {
        v.x = fmaxf(v.x, 0.f); v.y = fmaxf(v.y, 0.f);
        v.z = fmaxf(v.z, 0.f); v.w = fmaxf(v.w, 0.f);
    }
    *(float4*)(out + e) = v;
}

// ---------------------------------------------------------------------------
// bf16-split HMMA GEMM. CTA tile 128 x BNT, 8 warps (4m x 2n),
// warp tile 32 x (BNT/2). blockIdx.y = slice; SPLITS slices per operand pair.
// partial=1: raw fp32 partials to C + slice*PS. partial=0: bias/relu epilogue.
// ---------------------------------------------------------------------------
template<int BNT>
__global__ __launch_bounds__(NTH, 1)
void tgemm(const float* __restrict__ A1, int lda1, int ka1,
           const float* __restrict__ B1, int ldb1,
           const float* __restrict__ A2, int lda2, int ka2,
           const float* __restrict__ B2, int ldb2,
           int SPLITS,
           const float* __restrict__ bias, int bias_mode, int do_relu,
           int partial,
           float* __restrict__ C, int ldc, int Mreal)
{
    constexpr int NTW = BNT / 16;            // n8-tiles per warp (warp spans BNT/2)
    constexpr int PITCHB = BNT + 8;          // bf16 elems per B smem row
    constexpr int NBG = NTW / 2;             // B ldmatrix groups per term
    constexpr int FB = BNT / 16;             // float4s per thread for B load
    constexpr uint32_t AH_OFF = 0;
    constexpr uint32_t AL_OFF = BM * PITCHA * 2;             // 18432
    constexpr uint32_t BH_OFF = 2 * BM * PITCHA * 2;         // 36864
    constexpr uint32_t BBYTES = (uint32_t)BKC * PITCHB * 2;
    constexpr uint32_t BL_OFF = BH_OFF + BBYTES;
    constexpr uint32_t STAGE  = BH_OFF + 2 * BBYTES;

    extern __shared__ __align__(16) char dsm[];
    const uint32_t sb = smem_u32(dsm);

    const int tid = threadIdx.x;
    const int wid = tid >> 5;
    const int lid = tid & 31;
    const int ms = wid & 3;                  // 4 m-warps, base ms*32
    const int ns = wid >> 2;                 // 2 n-warps, base ns*(BNT/2)
    const int n0 = blockIdx.x * BNT;
    const int slice = blockIdx.y;

    // slice -> operand pair + k window
    const int pair = slice / SPLITS;
    const int q    = slice % SPLITS;
    const float* A = pair ? A2 : A1;
    const float* B = pair ? B2 : B1;
    const int lda = pair ? lda2 : lda1;
    const int ldb = pair ? ldb2 : ldb1;
    const int kaeff = (pair ? ka2 : ka1) / SPLITS;
    const int kbase = q * kaeff;
    const int T = kaeff / BKC;

    // A loader: 128 rows x 64 k fp32, float4, 8 passes (16 threads/row)
    const int alrow = tid >> 4;
    const int alc   = (tid & 15) * 4;
    // B loader: 64 k x BNT n; thread -> (k row, BNT/4 n)
    const int bkq = tid >> 2;
    const int bnq = (tid & 3) * (BNT / 4);

    float acc[2][NTW][4];
#pragma unroll
    for (int a = 0; a < 2; ++a)
#pragma unroll
        for (int b = 0; b < NTW; ++b)
#pragma unroll
            for (int c = 0; c < 4; ++c) acc[a][b][c] = 0.0f;

    // A fragment lane offsets (validated non-trans layout)
    const uint32_t aoffH = AH_OFF +
        (((uint32_t)(ms * 32 + (lid & 15)) * PITCHA) + ((lid >> 4) & 1) * 8u) * 2u;
    // B fragment lane offsets (validated trans layout, [k][n] smem)
    const uint32_t boff = BH_OFF +
        (((uint32_t)(lid & 15) * PITCHB) + (uint32_t)(ns * (BNT / 2) + (lid >> 4) * 8)) * 2u;

    float4 fa[8];
    float4 fbr[FB];
    const float4 f4z = make_float4(0.f, 0.f, 0.f, 0.f);

#define LOADG(T_)                                                              \
    do {                                                                       \
        int k0_ = kbase + (T_) * BKC;                                          \
        _Pragma("unroll")                                                      \
        for (int p = 0; p < 8; ++p) {                                          \
            int m = p * 16 + alrow;                                            \
            fa[p] = (m < Mreal) ? *(const float4*)(A + (size_t)m * lda + k0_ + alc) : f4z; \
        }                                                                      \
        const float* p_ = B + (size_t)(k0_ + bkq) * ldb + n0 + bnq;            \
        _Pragma("unroll")                                                      \
        for (int j = 0; j < FB; ++j)                                           \
            fbr[j] = *(const float4*)(p_ + j * 4);                             \
    } while (0)

#define STORE_STAGE(bufsel)                                                    \
    do {                                                                       \
        char* st = dsm + (bufsel) * STAGE;                                     \
        _Pragma("unroll")                                                      \
        for (int p = 0; p < 8; ++p) {                                          \
            int row = p * 16 + alrow;                                          \
            uint32_t h0, l0, h1, l1;                                           \
            split2(fa[p].x, fa[p].y, h0, l0);                                  \
            split2(fa[p].z, fa[p].w, h1, l1);                                  \
            uint32_t off = ((uint32_t)row * PITCHA + (uint32_t)alc) * 2u;      \
            *(uint2*)(st + AH_OFF + off) = make_uint2(h0, h1);                 \
            *(uint2*)(st + AL_OFF + off) = make_uint2(l0, l1);                 \
        }                                                                      \
        {                                                                      \
            uint32_t o_ = ((uint32_t)bkq * PITCHB + (uint32_t)bnq) * 2u;       \
            _Pragma("unroll")                                                  \
            for (int j = 0; j < FB; j += 2) {                                  \
                uint4 hv, lv;                                                  \
                split2(fbr[j].x,     fbr[j].y,     hv.x, lv.x);                \
                split2(fbr[j].z,     fbr[j].w,     hv.y, lv.y);                \
                split2(fbr[j + 1].x, fbr[j + 1].y, hv.z, lv.z);                \
                split2(fbr[j + 1].z, fbr[j + 1].w, hv.w, lv.w);                \
                *(uint4*)(st + BH_OFF + o_ + j * 8) = hv;                      \
                *(uint4*)(st + BL_OFF + o_ + j * 8) = lv;                      \
            }                                                                  \
        }                                                                      \
    } while (0)

    // ---- prologue ----
    LOADG(0);
    STORE_STAGE(0);
    if (T > 1) LOADG(1);
    __syncthreads();

    for (int t = 0; t < T; ++t) {
        const uint32_t base = sb + (uint32_t)(t & 1) * STAGE;

        // ---- MMA: 4 k-steps of 16 ----
#pragma unroll
        for (int ks = 0; ks < 4; ++ks) {
            const uint32_t kA = (uint32_t)ks * 32u;
            const uint32_t kB = (uint32_t)ks * 16u * PITCHB * 2u;
            uint32_t ah[2][4], al[2][4], bh[NBG][4], bl[NBG][4];
            LDMX4(ah[0], base + aoffH + kA);
            LDMX4(ah[1], base + aoffH + 16u * PITCHA * 2u + kA);
            LDMX4(al[0], base + aoffH + (AL_OFF - AH_OFF) + kA);
            LDMX4(al[1], base + aoffH + (AL_OFF - AH_OFF) + 16u * PITCHA * 2u + kA);
#pragma unroll
            for (int gp = 0; gp < NBG; ++gp) {
                LDMX4T(bh[gp], base + boff + gp * 32u + kB);
                LDMX4T(bl[gp], base + boff + (BL_OFF - BH_OFF) + gp * 32u + kB);
            }
#pragma unroll
            for (int mt = 0; mt < 2; ++mt)
#pragma unroll
                for (int nt = 0; nt < NTW; ++nt) {
                    const int gp = nt >> 1, ix = (nt & 1) * 2;
                    MMA_BF16(acc[mt][nt], ah[mt], bh[gp][ix], bh[gp][ix + 1]);
                    MMA_BF16(acc[mt][nt], ah[mt], bl[gp][ix], bl[gp][ix + 1]);
                    MMA_BF16(acc[mt][nt], al[mt], bh[gp][ix], bh[gp][ix + 1]);
                }
        }

        // ---- stage t+1, prefetch t+2 ----
        if (t + 1 < T) STORE_STAGE((t + 1) & 1);
        if (t + 2 < T) LOADG(t + 2);

        __syncthreads();
    }
#undef LOADG
#undef STORE_STAGE

    // ---- epilogue ----
    const int g  = lid >> 2;
    const int tq = lid & 3;
    float* Pout = C + (size_t)slice * PS;
#pragma unroll
    for (int mt = 0; mt < 2; ++mt) {
#pragma unroll
        for (int nt = 0; nt < NTW; ++nt) {
            int col = n0 + ns * (BNT / 2) + nt * 8 + tq * 2;
            float bc0 = 0.f, bc1 = 0.f;
            if (!partial && bias_mode == 1) { bc0 = bias[col]; bc1 = bias[col + 1]; }
#pragma unroll
            for (int half = 0; half < 2; ++half) {
                int m = ms * 32 + mt * 16 + g + half * 8;
                if (m >= Mreal) continue;
                float vx = acc[mt][nt][half * 2 + 0];
                float vy = acc[mt][nt][half * 2 + 1];
                if (partial) {
                    *(float2*)&Pout[(size_t)m * ldc + col] = make_float2(vx, vy);
                } else {
                    float rb = (bias_mode == 2) ? bias[m] : 0.0f;
                    vx += bc0 + rb;
                    vy += bc1 + rb;
                    if (do_relu) { vx = fmaxf(vx, 0.f); vy = fmaxf(vy, 0.f); }
                    *(float2*)&C[(size_t)m * ldc + col] = make_float2(vx, vy);
                }
            }
        }
    }
}

// ---------------------------------------------------------------------------
extern "C" void kernel_launch(void* const* d_in, const int* in_sizes, int n_in,
                              void* d_out, int out_size)
{
    const float* x   = (const float*)d_in[0];
    const int*   adj = (const int*)  d_in[1];
    const float* W2  = (const float*)d_in[2];
    const float* b2  = (const float*)d_in[3];
    const float* W1  = (const float*)d_in[4];
    const float* b1  = (const float*)d_in[5];
    const float* Wl  = (const float*)d_in[6];
    const float* bl  = (const float*)d_in[7];
    float* out = (float*)d_out;

    float *h, *aggr, *out1, *Mn, *Wlp, *P;
    cudaGetSymbolAddress((void**)&h,    g_h);
    cudaGetSymbolAddress((void**)&aggr, g_aggr);
    cudaGetSymbolAddress((void**)&out1, g_out1);
    cudaGetSymbolAddress((void**)&Mn,   g_Mn);
    cudaGetSymbolAddress((void**)&Wlp,  g_Wlp);
    cudaGetSymbolAddress((void**)&P,    g_P);

    // dynamic smem sizes
    const int DS64  = 2 * (2 * BM * PITCHA * 2 + 2 * BKC * (64 + 8) * 2);    // 110592
    const int DS128 = 2 * (2 * BM * PITCHA * 2 + 2 * BKC * (128 + 8) * 2);   // 143360
    cudaFuncSetAttribute(tgemm<64>,  cudaFuncAttributeMaxDynamicSharedMemorySize, DS64);
    cudaFuncSetAttribute(tgemm<128>, cudaFuncAttributeMaxDynamicSharedMemorySize, DS128);

    dim3 b(NTH);
    dim3 gBig(CC / 128, 4);   // 32 x 4 slices = 128 CTAs
    dim3 gSm (CC / 64, 1);    // 64 CTAs
    int cgrid = (NN * CC / 4 + 255) / 256;

    prep_kernel<<<NPAD, NPAD>>>(adj, Wl);

    // K1: P_s = x @ W2 over k slices of 1024 (s=0..3)
    tgemm<128><<<gBig, b, DS128>>>(x, CC, CC, W2, CC,
                                   nullptr, 0, 0, nullptr, 0,
                                   /*SPLITS=*/4,
                                   nullptr, 0, 0, /*partial=*/1,
                                   P, CC, NN);
    combine_kernel<<<cgrid, 256>>>(P, b2, 0, h);

    // K2: aggr = Mn @ h (direct)
    tgemm<64><<<gSm, b, DS64>>>(Mn, NPAD, NPAD, h, CC,
                                nullptr, 0, 0, nullptr, 0,
                                /*SPLITS=*/1,
                                nullptr, 0, 0, /*partial=*/0,
                                aggr, CC, NN);

    // K3: P_s = (h @ W1_top | aggr @ W1_bot), each pair split in 2 (s=0..3)
    tgemm<128><<<gBig, b, DS128>>>(h, CC, CC, W1, CC,
                                   aggr, CC, CC, W1 + (size_t)CC * CC, CC,
                                   /*SPLITS=*/2,
                                   nullptr, 0, 0, /*partial=*/1,
                                   P, CC, NN);
    combine_kernel<<<cgrid, 256>>>(P, b1, 1, out1);

    // K4: out = Wlp @ out1 + bl[:,None] (direct)
    tgemm<64><<<gSm, b, DS64>>>(Wlp, NPAD, NPAD, out1, CC,
                                nullptr, 0, 0, nullptr, 0,
                                /*SPLITS=*/1,
                                bl, 2, 0, /*partial=*/0,
                                out, CC, NN);
}